// round 1
// baseline (speedup 1.0000x reference)
#include <cuda_runtime.h>

// Problem constants (from reference): query [TOTAL,16,128] f32, key/value [TOTAL,4,128] f32,
// q_start_loc [B] i32, q_seqlens [B] i32. Output [TOTAL,16,128] f32.
#define HEADS   16
#define KVHEADS 4
#define DHEAD   128
#define WINDOW  1024
#define SOFTCAP 30.0f

#define BQ 64
#define BK 64
#define NTHREADS 256

// Q is pre-multiplied by SCALE/SOFTCAP so score = SOFTCAP * tanh(dot).
#define SCALE_OVER_CAP (0.08838834764831845f / 30.0f)
#define LOG2E 1.4426950408889634f
#define TWO_LOG2E 2.8853900817779268f

#define QT_STRIDE (BQ + 4)   // 68, transposed Q: QsT[k][row]
#define KT_STRIDE (BK + 4)   // 68, transposed K: KsT[k][row]
#define V_STRIDE  (DHEAD + 4)// 132, row-major V: Vs[row][d]
#define P_STRIDE  (BQ + 4)   // 68, transposed P: PsT[kcol][qrow]

#define SMEM_FLOATS (DHEAD*QT_STRIDE + DHEAD*KT_STRIDE + BK*V_STRIDE + BK*P_STRIDE + 3*BQ)
#define SMEM_BYTES  (SMEM_FLOATS * 4)

__global__ __launch_bounds__(NTHREADS, 1)
void fa_prefill_kernel(const float* __restrict__ query,
                       const float* __restrict__ key,
                       const float* __restrict__ value,
                       const int*   __restrict__ q_start_loc,
                       const int*   __restrict__ q_seqlens,
                       float* __restrict__ out)
{
    extern __shared__ float sm[];
    float* QsT   = sm;                       // [DHEAD][QT_STRIDE]
    float* KsT   = QsT + DHEAD * QT_STRIDE;  // [DHEAD][KT_STRIDE]
    float* Vs    = KsT + DHEAD * KT_STRIDE;  // [BK][V_STRIDE]
    float* PsT   = Vs  + BK * V_STRIDE;      // [BK][P_STRIDE]
    float* row_m = PsT + BK * P_STRIDE;      // [BQ]
    float* row_l = row_m + BQ;               // [BQ]
    float* row_a = row_l + BQ;               // [BQ]

    const int qt  = blockIdx.x;
    const int h   = blockIdx.y;
    const int b   = blockIdx.z;
    const int tid = threadIdx.x;
    const int tx  = tid & 15;   // 0..15
    const int ty  = tid >> 4;   // 0..15

    const int q_start  = q_start_loc[b];
    const int q_len    = q_seqlens[b];
    const int kv_start = q_start;       // self-attention prefill
    const int kv_len   = q_len;
    const int q0 = qt * BQ;
    if (q0 >= q_len) return;            // block-uniform, before any sync

    const int hk = h >> 2;              // GQA: head h -> kv head h/4

    // ---- Load Q tile into transposed smem, pre-scaled ----
    for (int idx = tid; idx < BQ * (DHEAD / 4); idx += NTHREADS) {
        const int r  = idx >> 5;        // 0..63
        const int c4 = idx & 31;        // 0..31 float4 chunks
        float4 v4 = make_float4(0.f, 0.f, 0.f, 0.f);
        if (q0 + r < q_len) {
            v4 = *reinterpret_cast<const float4*>(
                query + ((size_t)(q_start + q0 + r) * HEADS + h) * DHEAD + c4 * 4);
        }
        const int k = c4 * 4;
        QsT[(k + 0) * QT_STRIDE + r] = v4.x * SCALE_OVER_CAP;
        QsT[(k + 1) * QT_STRIDE + r] = v4.y * SCALE_OVER_CAP;
        QsT[(k + 2) * QT_STRIDE + r] = v4.z * SCALE_OVER_CAP;
        QsT[(k + 3) * QT_STRIDE + r] = v4.w * SCALE_OVER_CAP;
    }
    if (tid < BQ) { row_m[tid] = -1e30f; row_l[tid] = 0.f; }

    // Output accumulator: rows ty*4+i, cols tx*8+j
    float o[4][8];
    #pragma unroll
    for (int i = 0; i < 4; i++)
        #pragma unroll
        for (int j = 0; j < 8; j++) o[i][j] = 0.f;

    // Key tile range: causal upper bound = this q tile; window lower bound.
    int kj_lo = q0 - (WINDOW - 1); if (kj_lo < 0) kj_lo = 0;
    const int t0 = kj_lo >> 6;      // /BK
    const int t1 = qt;

    for (int kt = t0; kt <= t1; kt++) {
        __syncthreads();   // previous PV done; also makes Q visible on iter 1
        const int k0 = kt * BK;

        // ---- Load K (transposed) and V (row-major) tiles ----
        for (int idx = tid; idx < BK * (DHEAD / 4); idx += NTHREADS) {
            const int r  = idx >> 5;
            const int c4 = idx & 31;
            float4 kv4 = make_float4(0.f, 0.f, 0.f, 0.f);
            float4 vv4 = make_float4(0.f, 0.f, 0.f, 0.f);
            if (k0 + r < kv_len) {
                const size_t off = ((size_t)(kv_start + k0 + r) * KVHEADS + hk) * DHEAD + c4 * 4;
                kv4 = *reinterpret_cast<const float4*>(key + off);
                vv4 = *reinterpret_cast<const float4*>(value + off);
            }
            const int k = c4 * 4;
            KsT[(k + 0) * KT_STRIDE + r] = kv4.x;
            KsT[(k + 1) * KT_STRIDE + r] = kv4.y;
            KsT[(k + 2) * KT_STRIDE + r] = kv4.z;
            KsT[(k + 3) * KT_STRIDE + r] = kv4.w;
            *reinterpret_cast<float4*>(Vs + r * V_STRIDE + c4 * 4) = vv4;
        }
        __syncthreads();

        // ---- S = Q @ K^T (outer-product over k) ----
        float acc[4][4];
        #pragma unroll
        for (int i = 0; i < 4; i++)
            #pragma unroll
            for (int j = 0; j < 4; j++) acc[i][j] = 0.f;

        #pragma unroll 8
        for (int k = 0; k < DHEAD; k++) {
            const float4 a  = *reinterpret_cast<const float4*>(QsT + k * QT_STRIDE + (ty << 2));
            const float4 bb = *reinterpret_cast<const float4*>(KsT + k * KT_STRIDE + (tx << 2));
            const float av[4] = {a.x, a.y, a.z, a.w};
            const float bv[4] = {bb.x, bb.y, bb.z, bb.w};
            #pragma unroll
            for (int i = 0; i < 4; i++)
                #pragma unroll
                for (int j = 0; j < 4; j++)
                    acc[i][j] = fmaf(av[i], bv[j], acc[i][j]);
        }

        // ---- softcap + mask + row max ----
        float mloc[4] = {-1e30f, -1e30f, -1e30f, -1e30f};
        #pragma unroll
        for (int i = 0; i < 4; i++) {
            const int qi = q0 + (ty << 2) + i;
            #pragma unroll
            for (int j = 0; j < 4; j++) {
                const int kj = k0 + (tx << 2) + j;
                float x = acc[i][j];
                x = fminf(fmaxf(x, -12.f), 12.f);
                const float e = exp2f(x * TWO_LOG2E);
                float s = SOFTCAP * __fdividef(e - 1.f, e + 1.f);
                const bool ok = (kj <= qi) && ((qi - kj) < WINDOW) && (kj < kv_len);
                s = ok ? s : -1e30f;
                acc[i][j] = s;
                mloc[i] = fmaxf(mloc[i], s);
            }
        }
        #pragma unroll
        for (int off = 8; off >= 1; off >>= 1)
            #pragma unroll
            for (int i = 0; i < 4; i++)
                mloc[i] = fmaxf(mloc[i], __shfl_xor_sync(0xffffffffu, mloc[i], off, 16));

        // ---- online softmax update ----
        float mnew[4], lsum[4];
        #pragma unroll
        for (int i = 0; i < 4; i++) {
            const int r = (ty << 2) + i;
            mnew[i] = fmaxf(row_m[r], mloc[i]);
            lsum[i] = 0.f;
            #pragma unroll
            for (int j = 0; j < 4; j++) {
                const float p = exp2f((acc[i][j] - mnew[i]) * LOG2E);
                PsT[(k0 == k0 ? ((tx << 2) + j) : 0) * P_STRIDE + r] = p;
                lsum[i] += p;
            }
        }
        #pragma unroll
        for (int off = 8; off >= 1; off >>= 1)
            #pragma unroll
            for (int i = 0; i < 4; i++)
                lsum[i] += __shfl_xor_sync(0xffffffffu, lsum[i], off, 16);

        if (tx == 0) {
            #pragma unroll
            for (int i = 0; i < 4; i++) {
                const int r = (ty << 2) + i;
                const float a_ = exp2f((row_m[r] - mnew[i]) * LOG2E);
                row_m[r] = mnew[i];
                row_l[r] = row_l[r] * a_ + lsum[i];
                row_a[r] = a_;
            }
        }
        __syncthreads();

        // ---- O = O*alpha + P @ V ----
        float al[4];
        #pragma unroll
        for (int i = 0; i < 4; i++) al[i] = row_a[(ty << 2) + i];
        #pragma unroll
        for (int i = 0; i < 4; i++)
            #pragma unroll
            for (int j = 0; j < 8; j++) o[i][j] *= al[i];

        #pragma unroll 4
        for (int kk = 0; kk < BK; kk++) {
            const float4 p  = *reinterpret_cast<const float4*>(PsT + kk * P_STRIDE + (ty << 2));
            const float4 va = *reinterpret_cast<const float4*>(Vs + kk * V_STRIDE + (tx << 3));
            const float4 vb = *reinterpret_cast<const float4*>(Vs + kk * V_STRIDE + (tx << 3) + 4);
            const float pv[4] = {p.x, p.y, p.z, p.w};
            const float vv[8] = {va.x, va.y, va.z, va.w, vb.x, vb.y, vb.z, vb.w};
            #pragma unroll
            for (int i = 0; i < 4; i++)
                #pragma unroll
                for (int j = 0; j < 8; j++)
                    o[i][j] = fmaf(pv[i], vv[j], o[i][j]);
        }
    }

    // ---- Normalize and store (row_l was synced before the last PV phase) ----
    #pragma unroll
    for (int i = 0; i < 4; i++) {
        const int qi = q0 + (ty << 2) + i;
        if (qi < q_len) {
            const float inv = 1.0f / row_l[(ty << 2) + i];
            const size_t base = ((size_t)(q_start + qi) * HEADS + h) * DHEAD + (tx << 3);
            float4 r0 = make_float4(o[i][0] * inv, o[i][1] * inv, o[i][2] * inv, o[i][3] * inv);
            float4 r1 = make_float4(o[i][4] * inv, o[i][5] * inv, o[i][6] * inv, o[i][7] * inv);
            *reinterpret_cast<float4*>(out + base)     = r0;
            *reinterpret_cast<float4*>(out + base + 4) = r1;
        }
    }
}

extern "C" void kernel_launch(void* const* d_in, const int* in_sizes, int n_in,
                              void* d_out, int out_size)
{
    const float* query = (const float*)d_in[0];
    const float* key   = (const float*)d_in[1];
    const float* value = (const float*)d_in[2];
    const int* q_start_loc = (const int*)d_in[3];
    const int* q_seqlens   = (const int*)d_in[4];
    float* out = (float*)d_out;

    const int total = in_sizes[0] / (HEADS * DHEAD);
    const int batch = in_sizes[3];
    const int seqlen = total / batch;
    const int n_qtiles = (seqlen + BQ - 1) / BQ;

    cudaFuncSetAttribute(fa_prefill_kernel,
                         cudaFuncAttributeMaxDynamicSharedMemorySize, SMEM_BYTES);

    dim3 grid(n_qtiles, HEADS, batch);
    fa_prefill_kernel<<<grid, NTHREADS, SMEM_BYTES>>>(
        query, key, value, q_start_loc, q_seqlens, out);
}

// round 2
// speedup vs baseline: 1.4217x; 1.4217x over previous
#include <cuda_runtime.h>

// query [TOTAL,16,128] f32, key/value [TOTAL,4,128] f32, q_start_loc [B] i32,
// q_seqlens [B] i32 -> out [TOTAL,16,128] f32.
#define HEADS   16
#define KVHEADS 4
#define DHEAD   128
#define WINDOW  1024
#define SOFTCAP 30.0f

#define BQ 128
#define BK 64
#define NTHREADS 256

#define SCALE_OVER_CAP (0.08838834764831845f / 30.0f)
#define LOG2E 1.4426950408889634f
#define TWO_LOG2E 2.8853900817779268f

#define QT_STRIDE (BQ + 4)     // 132 : QsT[k][qrow]
#define KT_STRIDE (BK + 4)     // 68  : KsT[k][kcol]
#define V_STRIDE  (DHEAD + 4)  // 132 : Vs[krow][d]
#define P_STRIDE  (BQ + 4)     // 132 : PsT[kcol][qrow]

#define SMEM_FLOATS (DHEAD*QT_STRIDE + DHEAD*KT_STRIDE + BK*V_STRIDE + BK*P_STRIDE + 2*BQ)
#define SMEM_BYTES  (SMEM_FLOATS * 4)

typedef unsigned long long ull;

__device__ __forceinline__ ull pk2(float x, float y) {
    ull r;
    asm("mov.b64 %0, {%1, %2};" : "=l"(r)
        : "r"(__float_as_uint(x)), "r"(__float_as_uint(y)));
    return r;
}
__device__ __forceinline__ ull bc2(float x) { return pk2(x, x); }
__device__ __forceinline__ void up2(ull v, float& x, float& y) {
    unsigned lo, hi;
    asm("mov.b64 {%0, %1}, %2;" : "=r"(lo), "=r"(hi) : "l"(v));
    x = __uint_as_float(lo); y = __uint_as_float(hi);
}
__device__ __forceinline__ ull fma2(ull a, ull b, ull c) {
    ull d;
    asm("fma.rn.f32x2 %0, %1, %2, %3;" : "=l"(d) : "l"(a), "l"(b), "l"(c));
    return d;
}
__device__ __forceinline__ ull mul2(ull a, ull b) {
    ull d;
    asm("mul.rn.f32x2 %0, %1, %2;" : "=l"(d) : "l"(a), "l"(b));
    return d;
}

__global__ __launch_bounds__(NTHREADS, 1)
void fa_prefill_kernel(const float* __restrict__ query,
                       const float* __restrict__ key,
                       const float* __restrict__ value,
                       const int*   __restrict__ q_start_loc,
                       const int*   __restrict__ q_seqlens,
                       float* __restrict__ out)
{
    extern __shared__ float sm[];
    float* QsT   = sm;                       // [DHEAD][QT_STRIDE]
    float* KsT   = QsT + DHEAD * QT_STRIDE;  // [DHEAD][KT_STRIDE]
    float* Vs    = KsT + DHEAD * KT_STRIDE;  // [BK][V_STRIDE]
    float* PsT   = Vs  + BK * V_STRIDE;      // [BK][P_STRIDE]
    float* row_m = PsT + BK * P_STRIDE;      // [BQ]
    float* row_l = row_m + BQ;               // [BQ]

    const int qt  = blockIdx.x;
    const int h   = blockIdx.y;
    const int b   = blockIdx.z;
    const int tid = threadIdx.x;
    const int tx  = tid & 15;     // 0..15
    const int ty  = tid >> 4;     // 0..15
    const int r0  = ty << 3;      // 8 q-rows per thread
    const int c0  = tx << 2;      // 4 S-cols per thread (QK)
    const int d0  = tx << 3;      // 8 D-cols per thread (PV)

    const int q_start  = q_start_loc[b];
    const int q_len    = q_seqlens[b];
    const int kv_start = q_start;
    const int kv_len   = q_len;
    const int q0 = qt * BQ;
    if (q0 >= q_len) return;

    const int hk = h >> 2;

    // ---- Load Q tile -> transposed smem, pre-scaled ----
    for (int idx = tid; idx < BQ * (DHEAD / 4); idx += NTHREADS) {
        const int r  = idx >> 5;          // 0..127
        const int c4 = idx & 31;          // float4 chunk
        float4 v4 = make_float4(0.f, 0.f, 0.f, 0.f);
        if (q0 + r < q_len) {
            v4 = *reinterpret_cast<const float4*>(
                query + ((size_t)(q_start + q0 + r) * HEADS + h) * DHEAD + c4 * 4);
        }
        const int k = c4 * 4;
        QsT[(k + 0) * QT_STRIDE + r] = v4.x * SCALE_OVER_CAP;
        QsT[(k + 1) * QT_STRIDE + r] = v4.y * SCALE_OVER_CAP;
        QsT[(k + 2) * QT_STRIDE + r] = v4.z * SCALE_OVER_CAP;
        QsT[(k + 3) * QT_STRIDE + r] = v4.w * SCALE_OVER_CAP;
    }
    if (tid < BQ) { row_m[tid] = -1e30f; row_l[tid] = 0.f; }

    // O accumulator: rows r0+i (i<8), col pairs (d0+2jp, d0+2jp+1)
    ull o2[8][4];
    #pragma unroll
    for (int i = 0; i < 8; i++)
        #pragma unroll
        for (int jp = 0; jp < 4; jp++) o2[i][jp] = 0ULL;

    int kj_lo = q0 - (WINDOW - 1); if (kj_lo < 0) kj_lo = 0;
    const int t0 = kj_lo >> 6;
    int t1 = (q0 + BQ - 1) >> 6;
    const int t1cap = (kv_len - 1) >> 6;
    if (t1 > t1cap) t1 = t1cap;

    for (int kt = t0; kt <= t1; kt++) {
        __syncthreads();                // prev PV done with Vs; Q visible on iter 1
        const int k0 = kt * BK;

        // ---- Load K (transposed) + V (row-major) ----
        for (int idx = tid; idx < BK * (DHEAD / 4); idx += NTHREADS) {
            const int r  = idx >> 5;
            const int c4 = idx & 31;
            float4 kv4 = make_float4(0.f, 0.f, 0.f, 0.f);
            float4 vv4 = make_float4(0.f, 0.f, 0.f, 0.f);
            if (k0 + r < kv_len) {
                const size_t off = ((size_t)(kv_start + k0 + r) * KVHEADS + hk) * DHEAD + c4 * 4;
                kv4 = *reinterpret_cast<const float4*>(key + off);
                vv4 = *reinterpret_cast<const float4*>(value + off);
            }
            const int k = c4 * 4;
            KsT[(k + 0) * KT_STRIDE + r] = kv4.x;
            KsT[(k + 1) * KT_STRIDE + r] = kv4.y;
            KsT[(k + 2) * KT_STRIDE + r] = kv4.z;
            KsT[(k + 3) * KT_STRIDE + r] = kv4.w;
            *reinterpret_cast<float4*>(Vs + r * V_STRIDE + c4 * 4) = vv4;
        }
        __syncthreads();

        // ---- S = Q @ K^T, packed f32x2 (row pairs) ----
        ull acc2[4][4];
        #pragma unroll
        for (int ip = 0; ip < 4; ip++)
            #pragma unroll
            for (int j = 0; j < 4; j++) acc2[ip][j] = 0ULL;

        #pragma unroll 4
        for (int k = 0; k < DHEAD; k++) {
            const ulonglong2 qa = *reinterpret_cast<const ulonglong2*>(QsT + k * QT_STRIDE + r0);
            const ulonglong2 qb = *reinterpret_cast<const ulonglong2*>(QsT + k * QT_STRIDE + r0 + 4);
            const float4 kv = *reinterpret_cast<const float4*>(KsT + k * KT_STRIDE + c0);
            const ull ap[4] = {qa.x, qa.y, qb.x, qb.y};
            const ull bp[4] = {bc2(kv.x), bc2(kv.y), bc2(kv.z), bc2(kv.w)};
            #pragma unroll
            for (int ip = 0; ip < 4; ip++)
                #pragma unroll
                for (int j = 0; j < 4; j++)
                    acc2[ip][j] = fma2(ap[ip], bp[j], acc2[ip][j]);
        }

        // ---- softcap + mask + online softmax (warp-private rows) ----
        float p_s[8][4];
        float m8[8];
        #pragma unroll
        for (int i = 0; i < 8; i++) m8[i] = -1e30f;

        #pragma unroll
        for (int ip = 0; ip < 4; ip++) {
            #pragma unroll
            for (int j = 0; j < 4; j++) {
                float x0, x1;
                up2(acc2[ip][j], x0, x1);
                const int kj = k0 + c0 + j;
                {
                    const int i = 2 * ip;
                    const int qi = q0 + r0 + i;
                    float x = fminf(fmaxf(x0, -12.f), 12.f);
                    const float e = exp2f(x * TWO_LOG2E);
                    float s = SOFTCAP * __fdividef(e - 1.f, e + 1.f);
                    const bool ok = (kj <= qi) && ((qi - kj) < WINDOW) && (kj < kv_len);
                    s = ok ? s : -1e30f;
                    p_s[i][j] = s;
                    m8[i] = fmaxf(m8[i], s);
                }
                {
                    const int i = 2 * ip + 1;
                    const int qi = q0 + r0 + i;
                    float x = fminf(fmaxf(x1, -12.f), 12.f);
                    const float e = exp2f(x * TWO_LOG2E);
                    float s = SOFTCAP * __fdividef(e - 1.f, e + 1.f);
                    const bool ok = (kj <= qi) && ((qi - kj) < WINDOW) && (kj < kv_len);
                    s = ok ? s : -1e30f;
                    p_s[i][j] = s;
                    m8[i] = fmaxf(m8[i], s);
                }
            }
        }
        #pragma unroll
        for (int off = 8; off >= 1; off >>= 1)
            #pragma unroll
            for (int i = 0; i < 8; i++)
                m8[i] = fmaxf(m8[i], __shfl_xor_sync(0xffffffffu, m8[i], off, 16));

        float mnew[8], alpha[8], lsum[8];
        #pragma unroll
        for (int i = 0; i < 8; i++) {
            const float mo = row_m[r0 + i];
            mnew[i]  = fmaxf(mo, m8[i]);
            alpha[i] = exp2f((mo - mnew[i]) * LOG2E);
            lsum[i]  = 0.f;
            #pragma unroll
            for (int j = 0; j < 4; j++) {
                const float p = exp2f((p_s[i][j] - mnew[i]) * LOG2E);
                p_s[i][j] = p;
                lsum[i] += p;
            }
        }
        #pragma unroll
        for (int off = 8; off >= 1; off >>= 1)
            #pragma unroll
            for (int i = 0; i < 8; i++)
                lsum[i] += __shfl_xor_sync(0xffffffffu, lsum[i], off, 16);

        if (tx == 0) {
            #pragma unroll
            for (int i = 0; i < 8; i++) {
                row_m[r0 + i] = mnew[i];
                row_l[r0 + i] = row_l[r0 + i] * alpha[i] + lsum[i];
            }
        }

        // store P transposed: PsT[col][row], rows are warp-private
        #pragma unroll
        for (int j = 0; j < 4; j++) {
            float4 lo = make_float4(p_s[0][j], p_s[1][j], p_s[2][j], p_s[3][j]);
            float4 hi = make_float4(p_s[4][j], p_s[5][j], p_s[6][j], p_s[7][j]);
            *reinterpret_cast<float4*>(PsT + (c0 + j) * P_STRIDE + r0)     = lo;
            *reinterpret_cast<float4*>(PsT + (c0 + j) * P_STRIDE + r0 + 4) = hi;
        }
        __syncwarp();

        // ---- O = O*alpha + P @ V, packed f32x2 (col pairs) ----
        #pragma unroll
        for (int i = 0; i < 8; i++) {
            const ull a2 = bc2(alpha[i]);
            #pragma unroll
            for (int jp = 0; jp < 4; jp++) o2[i][jp] = mul2(o2[i][jp], a2);
        }

        #pragma unroll 2
        for (int kk = 0; kk < BK; kk++) {
            const float4 pa = *reinterpret_cast<const float4*>(PsT + kk * P_STRIDE + r0);
            const float4 pb = *reinterpret_cast<const float4*>(PsT + kk * P_STRIDE + r0 + 4);
            const ulonglong2 va = *reinterpret_cast<const ulonglong2*>(Vs + kk * V_STRIDE + d0);
            const ulonglong2 vb = *reinterpret_cast<const ulonglong2*>(Vs + kk * V_STRIDE + d0 + 4);
            const ull vp[4] = {va.x, va.y, vb.x, vb.y};
            const ull pp[8] = {bc2(pa.x), bc2(pa.y), bc2(pa.z), bc2(pa.w),
                               bc2(pb.x), bc2(pb.y), bc2(pb.z), bc2(pb.w)};
            #pragma unroll
            for (int i = 0; i < 8; i++)
                #pragma unroll
                for (int jp = 0; jp < 4; jp++)
                    o2[i][jp] = fma2(pp[i], vp[jp], o2[i][jp]);
        }
    }

    // ---- Normalize + store ----
    #pragma unroll
    for (int i = 0; i < 8; i++) {
        const int qi = q0 + r0 + i;
        if (qi < q_len) {
            const float inv = __fdividef(1.f, row_l[r0 + i]);
            float v[8];
            #pragma unroll
            for (int jp = 0; jp < 4; jp++) up2(o2[i][jp], v[2 * jp], v[2 * jp + 1]);
            const size_t base = ((size_t)(q_start + qi) * HEADS + h) * DHEAD + d0;
            float4 w0 = make_float4(v[0] * inv, v[1] * inv, v[2] * inv, v[3] * inv);
            float4 w1 = make_float4(v[4] * inv, v[5] * inv, v[6] * inv, v[7] * inv);
            *reinterpret_cast<float4*>(out + base)     = w0;
            *reinterpret_cast<float4*>(out + base + 4) = w1;
        }
    }
}

extern "C" void kernel_launch(void* const* d_in, const int* in_sizes, int n_in,
                              void* d_out, int out_size)
{
    const float* query = (const float*)d_in[0];
    const float* key   = (const float*)d_in[1];
    const float* value = (const float*)d_in[2];
    const int* q_start_loc = (const int*)d_in[3];
    const int* q_seqlens   = (const int*)d_in[4];
    float* out = (float*)d_out;

    const int total = in_sizes[0] / (HEADS * DHEAD);
    const int batch = in_sizes[3];
    const int seqlen = total / batch;
    const int n_qtiles = (seqlen + BQ - 1) / BQ;

    cudaFuncSetAttribute(fa_prefill_kernel,
                         cudaFuncAttributeMaxDynamicSharedMemorySize, SMEM_BYTES);

    dim3 grid(n_qtiles, HEADS, batch);
    fa_prefill_kernel<<<grid, NTHREADS, SMEM_BYTES>>>(
        query, key, value, q_start_loc, q_seqlens, out);
}

// round 5
// speedup vs baseline: 3.2088x; 2.2571x over previous
#include <cuda_runtime.h>
#include <cuda_bf16.h>

// query [TOTAL,16,128] f32, key/value [TOTAL,4,128] f32, q_start_loc [B] i32,
// q_seqlens [B] i32 -> out [TOTAL,16,128] f32.
#define HEADS   16
#define KVHEADS 4
#define DHEAD   128
#define WINDOW  1024
#define BQ 128
#define BK 64
#define NTHREADS 256

#define SCALE_OVER_CAP 0.0029462782549439484f   // (128^-0.5)/30
#define TWO_LOG2E 2.8853900817779268f
#define NEG_2CAP_LOG2E (-86.56170245333781f)    // -60*log2(e)

// smem byte offsets: bf16 tiles, rows of 128 bf16 (256B = 16 chunks of 16B),
// chunk-XOR swizzle for conflict-free ldmatrix.
#define QH_OFF 0        // [128][128] bf16 : 32768
#define QL_OFF 32768
#define KH_OFF 65536    // [64][128] bf16 : 16384
#define KL_OFF 81920
#define VH_OFF 98304    // [64][128] bf16 (natural [key][d])
#define VL_OFF 114688
#define SMEM_TOTAL 131072

typedef unsigned int u32;
typedef unsigned short u16;

static __device__ __forceinline__ u32 smem_u32(const void* p) {
    u32 a;
    asm("{ .reg .u64 t; cvta.to.shared.u64 t, %1; cvt.u32.u64 %0, t; }"
        : "=r"(a) : "l"(p));
    return a;
}
// byte offset of 16B chunk `chunk` in row `row` (128-bf16 rows, swizzled)
static __device__ __forceinline__ u32 swadr(int row, int chunk) {
    return (u32)((row << 8) + ((chunk ^ (row & 7)) << 4));
}

static __device__ __forceinline__ void ldsm4(u32 addr, u32 r[4]) {
    asm volatile("ldmatrix.sync.aligned.m8n8.x4.shared.b16 {%0,%1,%2,%3}, [%4];"
        : "=r"(r[0]), "=r"(r[1]), "=r"(r[2]), "=r"(r[3]) : "r"(addr));
}
static __device__ __forceinline__ void ldsm4t(u32 addr, u32 r[4]) {
    asm volatile("ldmatrix.sync.aligned.m8n8.x4.trans.shared.b16 {%0,%1,%2,%3}, [%4];"
        : "=r"(r[0]), "=r"(r[1]), "=r"(r[2]), "=r"(r[3]) : "r"(addr));
}
static __device__ __forceinline__ void mma_bf16(float c[4], const u32 a[4], const u32 b[2]) {
    asm volatile(
        "mma.sync.aligned.m16n8k16.row.col.f32.bf16.bf16.f32 "
        "{%0,%1,%2,%3}, {%4,%5,%6,%7}, {%8,%9}, {%0,%1,%2,%3};"
        : "+f"(c[0]), "+f"(c[1]), "+f"(c[2]), "+f"(c[3])
        : "r"(a[0]), "r"(a[1]), "r"(a[2]), "r"(a[3]), "r"(b[0]), "r"(b[1]));
}

// split 8 floats into hi/lo bf16 and store one 16B chunk each
static __device__ __forceinline__ void split8_store(char* smem, u32 hoff, u32 loff,
                                                    u32 off, const float* v) {
    u16 h[8], l[8];
    #pragma unroll
    for (int i = 0; i < 8; i++) {
        __nv_bfloat16 hb = __float2bfloat16_rn(v[i]);
        float r = v[i] - __bfloat162float(hb);
        h[i] = __bfloat16_as_ushort(hb);
        l[i] = __bfloat16_as_ushort(__float2bfloat16_rn(r));
    }
    uint4 H = make_uint4((u32)h[0] | ((u32)h[1] << 16), (u32)h[2] | ((u32)h[3] << 16),
                         (u32)h[4] | ((u32)h[5] << 16), (u32)h[6] | ((u32)h[7] << 16));
    uint4 L = make_uint4((u32)l[0] | ((u32)l[1] << 16), (u32)l[2] | ((u32)l[3] << 16),
                         (u32)l[4] | ((u32)l[5] << 16), (u32)l[6] | ((u32)l[7] << 16));
    *reinterpret_cast<uint4*>(smem + hoff + off) = H;
    *reinterpret_cast<uint4*>(smem + loff + off) = L;
}

__global__ __launch_bounds__(NTHREADS, 1)
void fa_mma_kernel(const float* __restrict__ query,
                   const float* __restrict__ key,
                   const float* __restrict__ value,
                   const int*   __restrict__ q_start_loc,
                   const int*   __restrict__ q_seqlens,
                   float* __restrict__ out)
{
    extern __shared__ char smch[];
    const u32 sb = smem_u32(smch);

    const int qt   = blockIdx.x;
    const int h    = blockIdx.y;
    const int b    = blockIdx.z;
    const int tid  = threadIdx.x;
    const int wid  = tid >> 5;
    const int lane = tid & 31;
    const int wrow = wid << 4;          // 16 q-rows per warp

    const int q_start  = q_start_loc[b];
    const int q_len    = q_seqlens[b];
    const int kv_start = q_start;
    const int kv_len   = q_len;
    const int q0 = qt * BQ;
    if (q0 >= q_len) return;
    const int hk = h >> 2;

    // ---- Load Q tile: f32 -> scaled -> bf16 hi/lo, swizzled ----
    for (int idx = tid; idx < BQ * 16; idx += NTHREADS) {
        const int row = idx >> 4;
        const int ch  = idx & 15;
        float v[8];
        #pragma unroll
        for (int i = 0; i < 8; i++) v[i] = 0.f;
        if (q0 + row < q_len) {
            const float* g = query + ((size_t)(q_start + q0 + row) * HEADS + h) * DHEAD + ch * 8;
            float4 a = *reinterpret_cast<const float4*>(g);
            float4 c = *reinterpret_cast<const float4*>(g + 4);
            v[0]=a.x; v[1]=a.y; v[2]=a.z; v[3]=a.w;
            v[4]=c.x; v[5]=c.y; v[6]=c.z; v[7]=c.w;
            #pragma unroll
            for (int i = 0; i < 8; i++) v[i] *= SCALE_OVER_CAP;
        }
        split8_store(smch, QH_OFF, QL_OFF, swadr(row, ch), v);
    }

    // ldmatrix lane-address precomputation
    const int mi = lane >> 3, mr = lane & 7;
    const int arow = wrow + mr + ((mi & 1) << 3);  // Q A-frag rows
    const int acb  = mi >> 1;                      // Q A-frag chunk base
    const int brow_off = ((mi >> 1) << 3) + mr;    // K B-frag row offset within n-tile pair
    const int bcb  = mi & 1;                       // K B-frag chunk base
    const int vrow_off = ((mi & 1) << 3) + mr;     // V(trans) row offset within k-step
    const int vcb  = mi >> 1;                      // V(trans) chunk base

    const int qi0 = q0 + wrow + (lane >> 2);
    const int qi1 = qi0 + 8;

    float oacc[16][4];
    #pragma unroll
    for (int i = 0; i < 16; i++)
        #pragma unroll
        for (int j = 0; j < 4; j++) oacc[i][j] = 0.f;
    float lq0 = 0.f, lq1 = 0.f;

    int kj_lo = q0 - (WINDOW - 1); if (kj_lo < 0) kj_lo = 0;
    const int t0 = kj_lo >> 6;
    int t1 = (q0 + BQ - 1) >> 6;
    const int t1cap = (kv_len - 1) >> 6;
    if (t1 > t1cap) t1 = t1cap;

    for (int kt = t0; kt <= t1; kt++) {
        const int k0 = kt * BK;
        __syncthreads();   // previous iteration's smem reads complete (covers Q store too)

        // ---- Load K & V tiles (same addressing) ----
        for (int idx = tid; idx < BK * 16; idx += NTHREADS) {
            const int row = idx >> 4;
            const int ch  = idx & 15;
            float kvv[8], vvv[8];
            #pragma unroll
            for (int i = 0; i < 8; i++) { kvv[i] = 0.f; vvv[i] = 0.f; }
            if (k0 + row < kv_len) {
                const size_t base = ((size_t)(kv_start + k0 + row) * KVHEADS + hk) * DHEAD + ch * 8;
                float4 a = *reinterpret_cast<const float4*>(key + base);
                float4 c = *reinterpret_cast<const float4*>(key + base + 4);
                kvv[0]=a.x; kvv[1]=a.y; kvv[2]=a.z; kvv[3]=a.w;
                kvv[4]=c.x; kvv[5]=c.y; kvv[6]=c.z; kvv[7]=c.w;
                a = *reinterpret_cast<const float4*>(value + base);
                c = *reinterpret_cast<const float4*>(value + base + 4);
                vvv[0]=a.x; vvv[1]=a.y; vvv[2]=a.z; vvv[3]=a.w;
                vvv[4]=c.x; vvv[5]=c.y; vvv[6]=c.z; vvv[7]=c.w;
            }
            const u32 off = swadr(row, ch);
            split8_store(smch, KH_OFF, KL_OFF, off, kvv);
            split8_store(smch, VH_OFF, VL_OFF, off, vvv);
        }
        __syncthreads();

        // ---- S = Q @ K^T : 8 n-tiles of width 8, fp32 accum ----
        float sacc[8][4];
        #pragma unroll
        for (int i = 0; i < 8; i++)
            #pragma unroll
            for (int j = 0; j < 4; j++) sacc[i][j] = 0.f;

        #pragma unroll
        for (int ks = 0; ks < 8; ks++) {          // k over dhead, 16 each
            u32 ah[4], al[4];
            const u32 aoff = swadr(arow, 2 * ks + acb);
            ldsm4(sb + QH_OFF + aoff, ah);
            ldsm4(sb + QL_OFF + aoff, al);
            #pragma unroll
            for (int ntp = 0; ntp < 4; ntp++) {   // n-tile pairs over keys
                u32 bh[4], bl[4];
                const u32 boff = swadr(16 * ntp + brow_off, 2 * ks + bcb);
                ldsm4(sb + KH_OFF + boff, bh);
                ldsm4(sb + KL_OFF + boff, bl);
                mma_bf16(sacc[2*ntp],   ah, &bh[0]);
                mma_bf16(sacc[2*ntp+1], ah, &bh[2]);
                mma_bf16(sacc[2*ntp],   al, &bh[0]);
                mma_bf16(sacc[2*ntp+1], al, &bh[2]);
                mma_bf16(sacc[2*ntp],   ah, &bl[0]);
                mma_bf16(sacc[2*ntp+1], ah, &bl[2]);
            }
        }

        // ---- epilogue: softcap + mask + p = exp(s-30); build PV A-frags ----
        u32 pah[4][4], pal[4][4];
        #pragma unroll
        for (int nt = 0; nt < 8; nt++) {
            const int kj = k0 + nt * 8 + ((lane & 3) << 1);
            float p[4];
            #pragma unroll
            for (int c = 0; c < 4; c++) {
                const int qi = (c < 2) ? qi0 : qi1;
                const int kc = kj + (c & 1);
                float x = fminf(fmaxf(sacc[nt][c], -12.f), 12.f);
                const float e = exp2f(x * TWO_LOG2E);
                float pv = exp2f(__fdividef(NEG_2CAP_LOG2E, e + 1.f));
                const bool ok = (kc <= qi) && ((qi - kc) < WINDOW) && (kc < kv_len);
                p[c] = ok ? pv : 0.f;
            }
            lq0 += p[0] + p[1];
            lq1 += p[2] + p[3];
            u16 hh[4], ll[4];
            #pragma unroll
            for (int c = 0; c < 4; c++) {
                __nv_bfloat16 hb = __float2bfloat16_rn(p[c]);
                float r = p[c] - __bfloat162float(hb);
                hh[c] = __bfloat16_as_ushort(hb);
                ll[c] = __bfloat16_as_ushort(__float2bfloat16_rn(r));
            }
            const int ks2 = nt >> 1;
            const int o   = (nt & 1) << 1;   // 0 -> regs a0,a1 ; 1 -> a2,a3
            pah[ks2][o]     = (u32)hh[0] | ((u32)hh[1] << 16);
            pah[ks2][o + 1] = (u32)hh[2] | ((u32)hh[3] << 16);
            pal[ks2][o]     = (u32)ll[0] | ((u32)ll[1] << 16);
            pal[ks2][o + 1] = (u32)ll[2] | ((u32)ll[3] << 16);
        }

        // ---- O += P @ V : 16 d n-tiles, V via ldmatrix.trans ----
        #pragma unroll
        for (int ks2 = 0; ks2 < 4; ks2++) {        // k over keys, 16 each
            #pragma unroll
            for (int dtp = 0; dtp < 8; dtp++) {    // d-tile pairs
                u32 bh[4], bl[4];
                const u32 voff = swadr(16 * ks2 + vrow_off, 2 * dtp + vcb);
                ldsm4t(sb + VH_OFF + voff, bh);
                ldsm4t(sb + VL_OFF + voff, bl);
                mma_bf16(oacc[2*dtp],   pah[ks2], &bh[0]);
                mma_bf16(oacc[2*dtp+1], pah[ks2], &bh[2]);
                mma_bf16(oacc[2*dtp],   pal[ks2], &bh[0]);
                mma_bf16(oacc[2*dtp+1], pal[ks2], &bh[2]);
                mma_bf16(oacc[2*dtp],   pah[ks2], &bl[0]);
                mma_bf16(oacc[2*dtp+1], pah[ks2], &bl[2]);
            }
        }
    }

    // ---- reduce l across the 4 lanes sharing each row, normalize, store ----
    lq0 += __shfl_xor_sync(0xffffffffu, lq0, 1);
    lq0 += __shfl_xor_sync(0xffffffffu, lq0, 2);
    lq1 += __shfl_xor_sync(0xffffffffu, lq1, 1);
    lq1 += __shfl_xor_sync(0xffffffffu, lq1, 2);
    const float inv0 = __fdividef(1.f, lq0);
    const float inv1 = __fdividef(1.f, lq1);

    const int colb = (lane & 3) << 1;
    if (qi0 < q_len) {
        float* g = out + ((size_t)(q_start + qi0) * HEADS + h) * DHEAD + colb;
        #pragma unroll
        for (int nt = 0; nt < 16; nt++)
            *reinterpret_cast<float2*>(g + nt * 8) =
                make_float2(oacc[nt][0] * inv0, oacc[nt][1] * inv0);
    }
    if (qi1 < q_len) {
        float* g = out + ((size_t)(q_start + qi1) * HEADS + h) * DHEAD + colb;
        #pragma unroll
        for (int nt = 0; nt < 16; nt++)
            *reinterpret_cast<float2*>(g + nt * 8) =
                make_float2(oacc[nt][2] * inv1, oacc[nt][3] * inv1);
    }
}

extern "C" void kernel_launch(void* const* d_in, const int* in_sizes, int n_in,
                              void* d_out, int out_size)
{
    const float* query = (const float*)d_in[0];
    const float* key   = (const float*)d_in[1];
    const float* value = (const float*)d_in[2];
    const int* q_start_loc = (const int*)d_in[3];
    const int* q_seqlens   = (const int*)d_in[4];
    float* out = (float*)d_out;

    const int total  = in_sizes[0] / (HEADS * DHEAD);
    const int batch  = in_sizes[3];
    const int seqlen = total / batch;
    const int n_qtiles = (seqlen + BQ - 1) / BQ;

    cudaFuncSetAttribute(fa_mma_kernel,
                         cudaFuncAttributeMaxDynamicSharedMemorySize, SMEM_TOTAL);

    dim3 grid(n_qtiles, HEADS, batch);
    fa_mma_kernel<<<grid, NTHREADS, SMEM_TOTAL>>>(
        query, key, value, q_start_loc, q_seqlens, out);
}

// round 6
// speedup vs baseline: 3.6467x; 1.1365x over previous
#include <cuda_runtime.h>
#include <cuda_bf16.h>

// query [TOTAL,16,128] f32, key/value [TOTAL,4,128] f32, q_start_loc [B] i32,
// q_seqlens [B] i32 -> out [TOTAL,16,128] f32.
#define HEADS   16
#define KVHEADS 4
#define DHEAD   128
#define WINDOW  1024
#define BQ 128
#define BK 64
#define NTHREADS 320          // 8 consumer warps + 2 producer warps

#define SCALE_OVER_CAP 0.0029462782549439484f   // (128^-0.5)/30
#define TWO_LOG2E 2.8853900817779268f
#define CAP_LOG2E 43.2808512266689f             // 30*log2(e)

// smem: bf16 tiles, rows of 128 bf16 (256B = 16 chunks of 16B), chunk-XOR swizzle.
#define QH_OFF 0          // [128][128] bf16 : 32768
#define QL_OFF 32768
#define KV_BASE 65536     // two 64KB buffers: {KH,KL,VH,VL} each 16384
#define KVBUF   65536
#define KH_R 0
#define KL_R 16384
#define VH_R 32768
#define VL_R 49152
#define SMEM_TOTAL 196608

// named barriers (id 0 = __syncthreads)
#define BAR_FULL0 1
#define BAR_FULL1 2
#define BAR_EMPTY0 3
#define BAR_EMPTY1 4
#define BAR_SYNC(id)   asm volatile("bar.sync %0, %1;"   :: "r"(id), "r"(NTHREADS) : "memory")
#define BAR_ARRIVE(id) asm volatile("bar.arrive %0, %1;" :: "r"(id), "r"(NTHREADS) : "memory")

typedef unsigned int u32;
typedef unsigned short u16;

static __device__ __forceinline__ u32 smem_u32(const void* p) {
    u32 a;
    asm("{ .reg .u64 t; cvta.to.shared.u64 t, %1; cvt.u32.u64 %0, t; }"
        : "=r"(a) : "l"(p));
    return a;
}
static __device__ __forceinline__ u32 swadr(int row, int chunk) {
    return (u32)((row << 8) + ((chunk ^ (row & 7)) << 4));
}
static __device__ __forceinline__ void ldsm4(u32 addr, u32 r[4]) {
    asm volatile("ldmatrix.sync.aligned.m8n8.x4.shared.b16 {%0,%1,%2,%3}, [%4];"
        : "=r"(r[0]), "=r"(r[1]), "=r"(r[2]), "=r"(r[3]) : "r"(addr));
}
static __device__ __forceinline__ void ldsm4t(u32 addr, u32 r[4]) {
    asm volatile("ldmatrix.sync.aligned.m8n8.x4.trans.shared.b16 {%0,%1,%2,%3}, [%4];"
        : "=r"(r[0]), "=r"(r[1]), "=r"(r[2]), "=r"(r[3]) : "r"(addr));
}
static __device__ __forceinline__ void mma_bf16(float c[4], const u32 a[4], const u32 b[2]) {
    asm volatile(
        "mma.sync.aligned.m16n8k16.row.col.f32.bf16.bf16.f32 "
        "{%0,%1,%2,%3}, {%4,%5,%6,%7}, {%8,%9}, {%0,%1,%2,%3};"
        : "+f"(c[0]), "+f"(c[1]), "+f"(c[2]), "+f"(c[3])
        : "r"(a[0]), "r"(a[1]), "r"(a[2]), "r"(a[3]), "r"(b[0]), "r"(b[1]));
}

// split (x0,x1) into packed bf16x2 hi and lo parts; low half = x0.
static __device__ __forceinline__ void splitpair(float x0, float x1, u32& hp, u32& lp) {
    u32 hpk;
    asm("cvt.rn.bf16x2.f32 %0, %1, %2;" : "=r"(hpk) : "f"(x1), "f"(x0));
    u32 f0, f1;
    asm("prmt.b32 %0, %1, 0, 0x1044;" : "=r"(f0) : "r"(hpk));
    asm("prmt.b32 %0, %1, 0, 0x3244;" : "=r"(f1) : "r"(hpk));
    float l0 = x0 - __uint_as_float(f0);
    float l1 = x1 - __uint_as_float(f1);
    asm("cvt.rn.bf16x2.f32 %0, %1, %2;" : "=r"(lp) : "f"(l1), "f"(l0));
    hp = hpk;
}
// split 8 floats, store one 16B chunk to hoff and loff
static __device__ __forceinline__ void split8_store(char* smem, u32 hoff, u32 loff,
                                                    u32 off, const float* v) {
    u32 h[4], l[4];
    splitpair(v[0], v[1], h[0], l[0]);
    splitpair(v[2], v[3], h[1], l[1]);
    splitpair(v[4], v[5], h[2], l[2]);
    splitpair(v[6], v[7], h[3], l[3]);
    *reinterpret_cast<uint4*>(smem + hoff + off) = make_uint4(h[0], h[1], h[2], h[3]);
    *reinterpret_cast<uint4*>(smem + loff + off) = make_uint4(l[0], l[1], l[2], l[3]);
}

__global__ __launch_bounds__(NTHREADS, 1)
void fa_ws_kernel(const float* __restrict__ query,
                  const float* __restrict__ key,
                  const float* __restrict__ value,
                  const int*   __restrict__ q_start_loc,
                  const int*   __restrict__ q_seqlens,
                  float* __restrict__ out)
{
    extern __shared__ char smch[];
    const u32 sb = smem_u32(smch);

    const int qt   = blockIdx.x;
    const int h    = blockIdx.y;
    const int b    = blockIdx.z;
    const int tid  = threadIdx.x;
    const int wid  = tid >> 5;
    const int lane = tid & 31;

    const int q_start  = q_start_loc[b];
    const int q_len    = q_seqlens[b];
    const int kv_start = q_start;
    const int kv_len   = q_len;
    const int q0 = qt * BQ;
    if (q0 >= q_len) return;
    const int hk = h >> 2;

    // ---- Q tile: all 320 threads cooperate; scaled, split hi/lo, swizzled ----
    for (int idx = tid; idx < BQ * 16; idx += NTHREADS) {
        const int row = idx >> 4;
        const int ch  = idx & 15;
        float v[8];
        #pragma unroll
        for (int i = 0; i < 8; i++) v[i] = 0.f;
        if (q0 + row < q_len) {
            const float* g = query + ((size_t)(q_start + q0 + row) * HEADS + h) * DHEAD + ch * 8;
            float4 a = *reinterpret_cast<const float4*>(g);
            float4 c = *reinterpret_cast<const float4*>(g + 4);
            v[0]=a.x; v[1]=a.y; v[2]=a.z; v[3]=a.w;
            v[4]=c.x; v[5]=c.y; v[6]=c.z; v[7]=c.w;
            #pragma unroll
            for (int i = 0; i < 8; i++) v[i] *= SCALE_OVER_CAP;
        }
        split8_store(smch, QH_OFF, QL_OFF, swadr(row, ch), v);
    }
    __syncthreads();

    int kj_lo = q0 - (WINDOW - 1); if (kj_lo < 0) kj_lo = 0;
    const int t0 = kj_lo >> 6;
    int t1 = (q0 + BQ - 1) >> 6;
    const int t1cap = (kv_len - 1) >> 6;
    if (t1 > t1cap) t1 = t1cap;

    if (wid >= 8) {
        // ================= PRODUCER (warps 8,9) =================
        const int ptid = (wid - 8) * 32 + lane;   // 0..63
        for (int kt = t0; kt <= t1; kt++) {
            const int bsel = (kt - t0) & 1;
            if (kt - t0 >= 2) BAR_SYNC(BAR_EMPTY0 + bsel);
            char* kvb = smch + KV_BASE + bsel * KVBUF;
            const int k0 = kt * BK;
            #pragma unroll 4
            for (int idx = ptid; idx < BK * 16; idx += 64) {
                const int row = idx >> 4;
                const int ch  = idx & 15;
                float kvv[8], vvv[8];
                #pragma unroll
                for (int i = 0; i < 8; i++) { kvv[i] = 0.f; vvv[i] = 0.f; }
                if (k0 + row < kv_len) {
                    const size_t base = ((size_t)(kv_start + k0 + row) * KVHEADS + hk) * DHEAD + ch * 8;
                    float4 a = *reinterpret_cast<const float4*>(key + base);
                    float4 c = *reinterpret_cast<const float4*>(key + base + 4);
                    kvv[0]=a.x; kvv[1]=a.y; kvv[2]=a.z; kvv[3]=a.w;
                    kvv[4]=c.x; kvv[5]=c.y; kvv[6]=c.z; kvv[7]=c.w;
                    a = *reinterpret_cast<const float4*>(value + base);
                    c = *reinterpret_cast<const float4*>(value + base + 4);
                    vvv[0]=a.x; vvv[1]=a.y; vvv[2]=a.z; vvv[3]=a.w;
                    vvv[4]=c.x; vvv[5]=c.y; vvv[6]=c.z; vvv[7]=c.w;
                }
                const u32 off = swadr(row, ch);
                split8_store(kvb, KH_R, KL_R, off, kvv);
                split8_store(kvb, VH_R, VL_R, off, vvv);
            }
            BAR_ARRIVE(BAR_FULL0 + bsel);
        }
        return;
    }

    // ================= CONSUMERS (warps 0..7) =================
    const int wrow = wid << 4;
    const int mi = lane >> 3, mr = lane & 7;
    const int arow = wrow + mr + ((mi & 1) << 3);
    const int acb  = mi >> 1;
    const int brow_off = ((mi >> 1) << 3) + mr;
    const int bcb  = mi & 1;
    const int vrow_off = ((mi & 1) << 3) + mr;
    const int vcb  = mi >> 1;

    const int qi0 = q0 + wrow + (lane >> 2);
    const int qi1 = qi0 + 8;

    float oacc[16][4];
    #pragma unroll
    for (int i = 0; i < 16; i++)
        #pragma unroll
        for (int j = 0; j < 4; j++) oacc[i][j] = 0.f;
    float lq0 = 0.f, lq1 = 0.f;

    for (int kt = t0; kt <= t1; kt++) {
        const int k0 = kt * BK;
        const int bsel = (kt - t0) & 1;
        BAR_SYNC(BAR_FULL0 + bsel);
        const u32 kvu = sb + KV_BASE + bsel * KVBUF;

        // ---- S = Q @ K^T : 3-term bf16 split, fp32 accum ----
        float sacc[8][4];
        #pragma unroll
        for (int i = 0; i < 8; i++)
            #pragma unroll
            for (int j = 0; j < 4; j++) sacc[i][j] = 0.f;

        #pragma unroll
        for (int ks = 0; ks < 8; ks++) {
            u32 ah[4], al[4];
            const u32 aoff = swadr(arow, 2 * ks + acb);
            ldsm4(sb + QH_OFF + aoff, ah);
            ldsm4(sb + QL_OFF + aoff, al);
            #pragma unroll
            for (int ntp = 0; ntp < 4; ntp++) {
                u32 bh[4], bl[4];
                const u32 boff = swadr(16 * ntp + brow_off, 2 * ks + bcb);
                ldsm4(kvu + KH_R + boff, bh);
                ldsm4(kvu + KL_R + boff, bl);
                mma_bf16(sacc[2*ntp],   ah, &bh[0]);
                mma_bf16(sacc[2*ntp+1], ah, &bh[2]);
                mma_bf16(sacc[2*ntp],   al, &bh[0]);
                mma_bf16(sacc[2*ntp+1], al, &bh[2]);
                mma_bf16(sacc[2*ntp],   ah, &bl[0]);
                mma_bf16(sacc[2*ntp+1], ah, &bl[2]);
            }
        }

        // ---- epilogue: p = exp(30*tanh(x) - 30); poly tanh, 1 MUFU/elem ----
        u32 pah[4][4], pal[4][4];
        #pragma unroll
        for (int nt = 0; nt < 8; nt++) {
            const int kj = k0 + nt * 8 + ((lane & 3) << 1);
            float p[4];
            #pragma unroll
            for (int c = 0; c < 4; c++) {
                const int qi = (c < 2) ? qi0 : qi1;
                const int kc = kj + (c & 1);
                const float x = sacc[nt][c];
                const float x2 = x * x;
                float th = x * fmaf(x2, fmaf(x2, 0.13333334f, -0.33333334f), 1.0f);
                if (x2 > 0.0625f) {           // |x| > 0.25 : ~never (x ~ N(0,1/900))
                    const float e = exp2f(x * TWO_LOG2E);
                    th = 1.f - __fdividef(2.f, e + 1.f);
                }
                float pv = exp2f(fmaf(th, CAP_LOG2E, -CAP_LOG2E));
                const bool ok = (kc <= qi) && ((qi - kc) < WINDOW) && (kc < kv_len);
                p[c] = ok ? pv : 0.f;
            }
            lq0 += p[0] + p[1];
            lq1 += p[2] + p[3];
            const int ks2 = nt >> 1;
            const int o   = (nt & 1) << 1;
            splitpair(p[0], p[1], pah[ks2][o],     pal[ks2][o]);
            splitpair(p[2], p[3], pah[ks2][o + 1], pal[ks2][o + 1]);
        }

        // ---- O += P @ V : 3-term split, V via ldmatrix.trans ----
        #pragma unroll
        for (int ks2 = 0; ks2 < 4; ks2++) {
            #pragma unroll
            for (int dtp = 0; dtp < 8; dtp++) {
                u32 bh[4], bl[4];
                const u32 voff = swadr(16 * ks2 + vrow_off, 2 * dtp + vcb);
                ldsm4t(kvu + VH_R + voff, bh);
                ldsm4t(kvu + VL_R + voff, bl);
                mma_bf16(oacc[2*dtp],   pah[ks2], &bh[0]);
                mma_bf16(oacc[2*dtp+1], pah[ks2], &bh[2]);
                mma_bf16(oacc[2*dtp],   pal[ks2], &bh[0]);
                mma_bf16(oacc[2*dtp+1], pal[ks2], &bh[2]);
                mma_bf16(oacc[2*dtp],   pah[ks2], &bl[0]);
                mma_bf16(oacc[2*dtp+1], pah[ks2], &bl[2]);
            }
        }
        BAR_ARRIVE(BAR_EMPTY0 + bsel);
    }

    // ---- reduce l across 4 lanes per row, normalize, store ----
    lq0 += __shfl_xor_sync(0xffffffffu, lq0, 1);
    lq0 += __shfl_xor_sync(0xffffffffu, lq0, 2);
    lq1 += __shfl_xor_sync(0xffffffffu, lq1, 1);
    lq1 += __shfl_xor_sync(0xffffffffu, lq1, 2);
    const float inv0 = __fdividef(1.f, lq0);
    const float inv1 = __fdividef(1.f, lq1);

    const int colb = (lane & 3) << 1;
    if (qi0 < q_len) {
        float* g = out + ((size_t)(q_start + qi0) * HEADS + h) * DHEAD + colb;
        #pragma unroll
        for (int nt = 0; nt < 16; nt++)
            *reinterpret_cast<float2*>(g + nt * 8) =
                make_float2(oacc[nt][0] * inv0, oacc[nt][1] * inv0);
    }
    if (qi1 < q_len) {
        float* g = out + ((size_t)(q_start + qi1) * HEADS + h) * DHEAD + colb;
        #pragma unroll
        for (int nt = 0; nt < 16; nt++)
            *reinterpret_cast<float2*>(g + nt * 8) =
                make_float2(oacc[nt][2] * inv1, oacc[nt][3] * inv1);
    }
}

extern "C" void kernel_launch(void* const* d_in, const int* in_sizes, int n_in,
                              void* d_out, int out_size)
{
    const float* query = (const float*)d_in[0];
    const float* key   = (const float*)d_in[1];
    const float* value = (const float*)d_in[2];
    const int* q_start_loc = (const int*)d_in[3];
    const int* q_seqlens   = (const int*)d_in[4];
    float* out = (float*)d_out;

    const int total  = in_sizes[0] / (HEADS * DHEAD);
    const int batch  = in_sizes[3];
    const int seqlen = total / batch;
    const int n_qtiles = (seqlen + BQ - 1) / BQ;

    cudaFuncSetAttribute(fa_ws_kernel,
                         cudaFuncAttributeMaxDynamicSharedMemorySize, SMEM_TOTAL);

    dim3 grid(n_qtiles, HEADS, batch);
    fa_ws_kernel<<<grid, NTHREADS, SMEM_TOTAL>>>(
        query, key, value, q_start_loc, q_seqlens, out);
}